// round 10
// baseline (speedup 1.0000x reference)
#include <cuda_runtime.h>
#include <cstdint>

#define NB    128
#define TPB   512
#define HID   512
#define BAT   128
#define T_IN  512
#define TT    544          // T_IN + future(32)

// smem layout (float offsets)
#define OW1   0            // W_hh1^T  [512][20] (16 rows used, stride 20 conflict-free)
#define OW2   10240        // W_ih2^T
#define OW3   20480        // W_hh2^T
#define OGA   30720        // gate buffer layer1 [16][128]
#define OGB   32768        // gate buffer layer2 [16][128]
#define OC1   34816        // c1 state [4][128]
#define OC2   35328        // c2 state [4][128]
#define OCB1  35840        // bias1 [16]
#define OCW1  35856        // wih1  [16]
#define OCB2  35872        // bias2 [16]
#define OCWO  35888        // wout  [4]
#define SMF   35904        // 143,616 bytes

__device__ float    g_h1[2][HID * BAT];
__device__ float    g_h2[2][HID * BAT];
__device__ unsigned g_bar;

using ull = unsigned long long;

__device__ __forceinline__ ull pk2(float w) {
    ull r; asm("mov.b64 %0, {%1, %1};" : "=l"(r) : "f"(w)); return r;
}
__device__ __forceinline__ void fma2(ull &a, ull w, ull h) {
    asm("fma.rn.f32x2 %0, %1, %2, %0;" : "+l"(a) : "l"(w), "l"(h));
}
__device__ __forceinline__ ull add2(ull a, ull b) {
    ull r; asm("add.rn.f32x2 %0, %1, %2;" : "=l"(r) : "l"(a), "l"(b)); return r;
}
__device__ __forceinline__ float2 unpk(ull v) {
    float2 f; asm("mov.b64 {%0, %1}, %2;" : "=f"(f.x), "=f"(f.y) : "l"(v)); return f;
}
// 16B L2-only global load (bypasses L1 -> coherent with other SMs' stores)
__device__ __forceinline__ ulonglong2 ldcg128(const float* p) {
    ulonglong2 r;
    asm volatile("ld.global.cg.v2.u64 {%0, %1}, [%2];"
                 : "=l"(r.x), "=l"(r.y) : "l"(p));
    return r;
}
__device__ __forceinline__ float ldcg32(const float* p) {
    float v;
    asm volatile("ld.global.cg.f32 %0, [%1];" : "=f"(v) : "l"(p));
    return v;
}
__device__ __forceinline__ float sigf(float v) { return 1.0f / (1.0f + expf(-v)); }

// grid barrier: all 128 blocks co-resident (1 block/SM). The __threadfence
// also invalidates L1 (fence scope >= cluster -> CCTL.IVALL), keeping any
// L1-cached reads safe.
__device__ __forceinline__ void grid_barrier(unsigned target) {
    __syncthreads();
    __threadfence();
    if (threadIdx.x == 0) {
        atomicAdd(&g_bar, 1u);
        unsigned v;
        do {
            asm volatile("ld.acquire.gpu.global.u32 %0, [%1];"
                         : "=r"(v) : "l"(&g_bar) : "memory");
        } while (v < target);
    }
    __syncthreads();
    __threadfence();
}

// One K=512 accumulation pass, h read directly from L2:
// acc[r][p] += sum_k wT[k][rg8+r] * h[k][bg8 + 2p .. 2p+1]
// Thread tile 8 rows x 8 batches, 16-way k-slice (lane bits 0-3).
__device__ __forceinline__ void pass_accum(
    const float* __restrict__ hsrc,   // global [512][128]
    const float* __restrict__ wT,     // smem k-major [512][20]
    ull acc[8][4], int rg8, int bg8, int slice)
{
    #pragma unroll 4
    for (int ii = 0; ii < 32; ii++) {
        int k = (ii << 4) + slice;
        const float* hp = hsrc + (k << 7) + bg8;
        ulonglong2 ha = ldcg128(hp);       // batches bg8+0..3
        ulonglong2 hc = ldcg128(hp + 4);   // batches bg8+4..7
        ull hv[4] = { ha.x, ha.y, hc.x, hc.y };

        const float* wk = wT + k * 20 + rg8;
        float4 w0 = *reinterpret_cast<const float4*>(wk);
        {
            ull wr[4] = { pk2(w0.x), pk2(w0.y), pk2(w0.z), pk2(w0.w) };
            #pragma unroll
            for (int r = 0; r < 4; r++)
                #pragma unroll
                for (int p = 0; p < 4; p++)
                    fma2(acc[r][p], wr[r], hv[p]);
        }
        float4 w1 = *reinterpret_cast<const float4*>(wk + 4);
        {
            ull wr[4] = { pk2(w1.x), pk2(w1.y), pk2(w1.z), pk2(w1.w) };
            #pragma unroll
            for (int r = 0; r < 4; r++)
                #pragma unroll
                for (int p = 0; p < 4; p++)
                    fma2(acc[4 + r][p], wr[r], hv[p]);
        }
    }
}

// Distributed butterfly reduction over the 16 k-slices (lane bits 0-3).
// Values stay live on all lanes; each round halves the set, selecting the
// half this lane keeps by its lane bit. 60 shfls (vs 128 naive); each lane
// ends owning 2 of the warp's 32 results and stores them itself.
__device__ __forceinline__ void reduce_to_gbuf(
    ull acc[8][4], float* gbuf, int rg8, int bg8, int lane)
{
    ull* v = &acc[0][0];   // flattened: index i = r*4 + p, i in [0,32)
    int live = 32;
    #pragma unroll
    for (int m = 0; m < 4; m++) {
        int half = live >> 1;
        int mask = 1 << m;
        bool hi = (lane >> m) & 1;
        #pragma unroll
        for (int j = 0; j < half; j++) {
            ull lo_s = add2(v[j],        __shfl_xor_sync(0xffffffffu, v[j],        mask));
            ull hi_s = add2(v[j + half], __shfl_xor_sync(0xffffffffu, v[j + half], mask));
            v[j] = hi ? hi_s : lo_s;
        }
        live = half;
    }
    int s = lane & 15;
    int base = ((s & 1) << 4) | (((s >> 1) & 1) << 3) |
               (((s >> 2) & 1) << 2) | (((s >> 3) & 1) << 1);
    #pragma unroll
    for (int j = 0; j < 2; j++) {
        int i = base + j;                       // original index r*4+p
        float2 f = unpk(v[j]);
        *reinterpret_cast<float2*>(gbuf + (rg8 + (i >> 2)) * BAT + bg8 + 2 * (i & 3)) = f;
    }
}

__global__ void init_kernel(float* __restrict__ out, const float* __restrict__ b_out) {
    int i = blockIdx.x * blockDim.x + threadIdx.x;
    if (i == 0) g_bar = 0u;
    if (i < HID * BAT) { g_h1[0][i] = 0.0f; g_h2[0][i] = 0.0f; }
    if (i < BAT * TT)  out[i] = b_out[0];
}

__global__ void __launch_bounds__(TPB, 1)
lstm_persistent_kernel(
    const float* __restrict__ x,
    const float* __restrict__ W_ih1, const float* __restrict__ W_hh1,
    const float* __restrict__ b_ih1, const float* __restrict__ b_hh1,
    const float* __restrict__ W_ih2, const float* __restrict__ W_hh2,
    const float* __restrict__ b_ih2, const float* __restrict__ b_hh2,
    const float* __restrict__ W_out, float* __restrict__ out)
{
    extern __shared__ float sm[];
    const int tid  = threadIdx.x;
    const int blk  = blockIdx.x;
    const int lane = tid & 31;
    const int warp = tid >> 5;          // 16 warps

    const int slice = lane & 15;        // k-slice (16-way)
    const int rg8   = (lane >> 4) << 3; // row base: 0 or 8
    const int bg8   = warp << 3;        // batch base (warp-uniform)

    // cell-update mapping: one (unit, batch) per thread
    const int cu = tid >> 7;            // unit 0..3
    const int cb = tid & 127;           // batch 0..127

    // ---- one-time setup: weights -> smem k-major (stride 20), consts, states
    for (int idx = tid; idx < 16 * HID; idx += TPB) {
        int r = idx >> 9, k = idx & 511;               // r = gate*4 + unit
        int row = ((r >> 2) * HID) + blk * 4 + (r & 3);
        sm[OW1 + k * 20 + r] = W_hh1[row * HID + k];
        sm[OW2 + k * 20 + r] = W_ih2[row * HID + k];
        sm[OW3 + k * 20 + r] = W_hh2[row * HID + k];
    }
    if (tid < 16) {
        int row = ((tid >> 2) * HID) + blk * 4 + (tid & 3);
        sm[OCB1 + tid] = b_ih1[row] + b_hh1[row];
        sm[OCW1 + tid] = W_ih1[row];                   // F = 1
        sm[OCB2 + tid] = b_ih2[row] + b_hh2[row];
    }
    if (tid < 4) sm[OCWO + tid] = W_out[blk * 4 + tid];
    for (int idx = tid; idx < 4 * BAT; idx += TPB) {
        sm[OC1 + idx] = 0.0f;
        sm[OC2 + idx] = 0.0f;
    }
    __syncthreads();

    float* gA = sm + OGA;
    float* gB = sm + OGB;
    unsigned ep = 0;
    int p = 0;

    for (int t = 0; t < TT; t++) {
        // ================= layer 1 =================
        ull acc[8][4];
        #pragma unroll
        for (int r = 0; r < 8; r++)
            #pragma unroll
            for (int q = 0; q < 4; q++) acc[r][q] = 0ull;

        float xv = 0.0f;
        if (t < T_IN) xv = x[cb * T_IN + t];

        pass_accum(g_h1[p], sm + OW1, acc, rg8, bg8, slice);
        reduce_to_gbuf(acc, gA, rg8, bg8, lane);
        __syncthreads();

        if (t >= T_IN) {
            // cell1 reads out(t-1): needs all blocks' PhaseB(t-1) atomics.
            grid_barrier(++ep * NB);
            xv = ldcg32(&out[cb * TT + (t - 1)]);
        }

        {
            float gi = gA[(cu)      * BAT + cb] + xv * sm[OCW1 + cu]      + sm[OCB1 + cu];
            float gf = gA[(4 + cu)  * BAT + cb] + xv * sm[OCW1 + 4 + cu]  + sm[OCB1 + 4 + cu];
            float gg = gA[(8 + cu)  * BAT + cb] + xv * sm[OCW1 + 8 + cu]  + sm[OCB1 + 8 + cu];
            float go = gA[(12 + cu) * BAT + cb] + xv * sm[OCW1 + 12 + cu] + sm[OCB1 + 12 + cu];
            float cc = sm[OC1 + cu * BAT + cb];
            float cn = sigf(gf) * cc + sigf(gi) * tanhf(gg);
            float hn = sigf(go) * tanhf(cn);
            sm[OC1 + cu * BAT + cb] = cn;
            g_h1[p ^ 1][(blk * 4 + cu) * BAT + cb] = hn;
        }
        grid_barrier(++ep * NB);   // the one mandatory barrier per step

        // ================= layer 2 (K=1024 across two sources) ===========
        #pragma unroll
        for (int r = 0; r < 8; r++)
            #pragma unroll
            for (int q = 0; q < 4; q++) acc[r][q] = 0ull;

        pass_accum(g_h1[p ^ 1], sm + OW2, acc, rg8, bg8, slice);
        pass_accum(g_h2[p],     sm + OW3, acc, rg8, bg8, slice);
        reduce_to_gbuf(acc, gB, rg8, bg8, lane);
        __syncthreads();

        {
            float gi = gB[(cu)      * BAT + cb] + sm[OCB2 + cu];
            float gf = gB[(4 + cu)  * BAT + cb] + sm[OCB2 + 4 + cu];
            float gg = gB[(8 + cu)  * BAT + cb] + sm[OCB2 + 8 + cu];
            float go = gB[(12 + cu) * BAT + cb] + sm[OCB2 + 12 + cu];
            float cc = sm[OC2 + cu * BAT + cb];
            float cn = sigf(gf) * cc + sigf(gi) * tanhf(gg);
            float hn = sigf(go) * tanhf(cn);
            sm[OC2 + cu * BAT + cb] = cn;
            g_h2[p ^ 1][(blk * 4 + cu) * BAT + cb] = hn;
            gB[cu * BAT + cb] = hn * sm[OCWO + cu];   // per-thread output partial
        }
        __syncthreads();
        if (tid < BAT) {
            float v = gB[tid] + gB[BAT + tid] + gB[2 * BAT + tid] + gB[3 * BAT + tid];
            atomicAdd(&out[tid * TT + t], v);
        }
        // no trailing grid barrier: PhaseA(t+1) only reads h1(t), synced at
        // this step's barrier; h2(t)/out(t) readers are ordered by the next
        // step's barriers.
        p ^= 1;
    }
}

extern "C" void kernel_launch(void* const* d_in, const int* in_sizes, int n_in,
                              void* d_out, int out_size) {
    const float* x     = (const float*)d_in[0];
    const float* W_ih1 = (const float*)d_in[1];
    const float* W_hh1 = (const float*)d_in[2];
    const float* b_ih1 = (const float*)d_in[3];
    const float* b_hh1 = (const float*)d_in[4];
    const float* W_ih2 = (const float*)d_in[5];
    const float* W_hh2 = (const float*)d_in[6];
    const float* b_ih2 = (const float*)d_in[7];
    const float* b_hh2 = (const float*)d_in[8];
    const float* W_out = (const float*)d_in[9];
    const float* b_out = (const float*)d_in[10];
    float* out = (float*)d_out;

    cudaFuncSetAttribute(lstm_persistent_kernel,
                         cudaFuncAttributeMaxDynamicSharedMemorySize, SMF * 4);

    init_kernel<<<(BAT * TT + 255) / 256, 256>>>(out, b_out);
    lstm_persistent_kernel<<<NB, TPB, SMF * 4>>>(
        x, W_ih1, W_hh1, b_ih1, b_hh1,
        W_ih2, W_hh2, b_ih2, b_hh2, W_out, out);
}

// round 13
// speedup vs baseline: 2.4985x; 2.4985x over previous
#include <cuda_runtime.h>
#include <cstdint>

#define NB    128
#define TPB   512
#define HID   512
#define BAT   128
#define T_IN  512
#define TT    544          // T_IN + future(32)

// smem layout (float offsets)
#define OW1   0            // W_hh1^T  [512][20] (16 rows used, stride 20 conflict-free)
#define OW2   10240        // W_ih2^T
#define OW3   20480        // W_hh2^T
#define OHB   30720        // warp-private h staging: 16 warps x 2 bufs x 512 floats
#define OGA   47104        // gate buffer layer1 [16][128]
#define OGB   49152        // gate buffer layer2 [16][128]
#define OC1   51200        // c1 state [4][128]
#define OC2   51712        // c2 state [4][128]
#define OCB1  52224        // bias1 [16]
#define OCW1  52240        // wih1  [16]
#define OCB2  52256        // bias2 [16]
#define OCWO  52272        // wout  [4]
#define SMF   52288        // 209,152 bytes

__device__ float    g_h1[2][HID * BAT];
__device__ float    g_h2[2][HID * BAT];
__device__ unsigned g_bar;

using ull = unsigned long long;

__device__ __forceinline__ ull pk2(float w) {
    ull r; asm("mov.b64 %0, {%1, %1};" : "=l"(r) : "f"(w)); return r;
}
__device__ __forceinline__ void fma2(ull &a, ull w, ull h) {
    asm("fma.rn.f32x2 %0, %1, %2, %0;" : "+l"(a) : "l"(w), "l"(h));
}
__device__ __forceinline__ ull add2(ull a, ull b) {
    ull r; asm("add.rn.f32x2 %0, %1, %2;" : "=l"(r) : "l"(a), "l"(b)); return r;
}
__device__ __forceinline__ float2 unpk(ull v) {
    float2 f; asm("mov.b64 {%0, %1}, %2;" : "=f"(f.x), "=f"(f.y) : "l"(v)); return f;
}
__device__ __forceinline__ void cp16(float* dst, const float* src) {
    unsigned d = (unsigned)__cvta_generic_to_shared(dst);
    asm volatile("cp.async.cg.shared.global [%0], [%1], 16;" :: "r"(d), "l"(src));
}
__device__ __forceinline__ float ldcg32(const float* p) {
    float v;
    asm volatile("ld.global.cg.f32 %0, [%1];" : "=f"(v) : "l"(p));
    return v;
}
__device__ __forceinline__ float sigf(float v) { return 1.0f / (1.0f + expf(-v)); }

// grid barrier: all 128 blocks co-resident (1 block/SM, forced by smem)
__device__ __forceinline__ void grid_barrier(unsigned target) {
    __syncthreads();
    __threadfence();
    if (threadIdx.x == 0) {
        atomicAdd(&g_bar, 1u);
        unsigned v;
        do {
            asm volatile("ld.acquire.gpu.global.u32 %0, [%1];"
                         : "=r"(v) : "l"(&g_bar) : "memory");
        } while (v < target);
    }
    __syncthreads();
    __threadfence();
}

// One K=512 pass, per-warp independent (no block syncs):
// acc[r][p] += sum_k wT[k][rg8+r] * h[k][bg8 + 2p .. 2p+1]
// Thread tile 8 rows x 8 batches, 16-way k-slice. h staged per warp via
// cp.async into a 2-deep private ring, XOR-swizzled for conflict-free LDS.128.
__device__ __forceinline__ void pass_accum(
    const float* __restrict__ hsrc,   // global [512][128]
    const float* __restrict__ wT,     // smem k-major [512][20]
    float* __restrict__ wb,           // warp-private staging (1024 floats)
    ull acc[8][4], int rg8, int bg8, int slice, int lane)
{
    // stage chunk 0 (64 k x 8 b = 2KB per warp; 4 x 16B per lane)
    #pragma unroll
    for (int q = 0; q < 4; q++) {
        int idx = lane + (q << 5);
        int kl = idx >> 1, j = idx & 1;
        int dst = (kl << 3) + (((j ^ (kl >> 2)) & 1) << 2);
        cp16(wb + dst, hsrc + kl * BAT + bg8 + (j << 2));
    }
    asm volatile("cp.async.commit_group;");

    const int sw = (slice >> 2) & 1;

    for (int c = 0; c < 8; c++) {
        if (c < 7) {
            const float* s  = hsrc + (c + 1) * (64 * BAT);
            float*       nx = wb + ((c + 1) & 1) * 512;
            #pragma unroll
            for (int q = 0; q < 4; q++) {
                int idx = lane + (q << 5);
                int kl = idx >> 1, j = idx & 1;
                int dst = (kl << 3) + (((j ^ (kl >> 2)) & 1) << 2);
                cp16(nx + dst, s + kl * BAT + bg8 + (j << 2));
            }
            asm volatile("cp.async.commit_group;");
            asm volatile("cp.async.wait_group 1;");
        } else {
            asm volatile("cp.async.wait_group 0;");
        }
        __syncwarp();   // make staged data visible to all lanes of this warp

        const float* cur = wb + (c & 1) * 512;
        #pragma unroll
        for (int ii = 0; ii < 4; ii++) {
            int kl = (ii << 4) + slice;
            // logical batch half j stored at physical half j ^ ((kl>>2)&1) = j ^ sw
            const ulonglong2 ha =
                *reinterpret_cast<const ulonglong2*>(cur + (kl << 3) + (sw << 2));
            const ulonglong2 hc =
                *reinterpret_cast<const ulonglong2*>(cur + (kl << 3) + ((sw ^ 1) << 2));
            ull hv[4] = { ha.x, ha.y, hc.x, hc.y };

            int kg = (c << 6) + kl;
            const float* wk = wT + kg * 20 + rg8;
            float4 w0 = *reinterpret_cast<const float4*>(wk);
            {
                ull wr[4] = { pk2(w0.x), pk2(w0.y), pk2(w0.z), pk2(w0.w) };
                #pragma unroll
                for (int r = 0; r < 4; r++)
                    #pragma unroll
                    for (int p = 0; p < 4; p++)
                        fma2(acc[r][p], wr[r], hv[p]);
            }
            float4 w1 = *reinterpret_cast<const float4*>(wk + 4);
            {
                ull wr[4] = { pk2(w1.x), pk2(w1.y), pk2(w1.z), pk2(w1.w) };
                #pragma unroll
                for (int r = 0; r < 4; r++)
                    #pragma unroll
                    for (int p = 0; p < 4; p++)
                        fma2(acc[4 + r][p], wr[r], hv[p]);
            }
        }
        // no trailing sync: all lanes' reads of this buffer precede (in the
        // convergent stream) any lane's cp.async overwriting it 2 chunks later.
    }
}

// Distributed butterfly reduction over the 16 k-slices (lane bits 0-3).
// 60 shfls; each lane ends owning 2 of the warp's 32 results and stores them.
__device__ __forceinline__ void reduce_to_gbuf(
    ull acc[8][4], float* gbuf, int rg8, int bg8, int lane)
{
    ull* v = &acc[0][0];   // flattened: index i = r*4 + p, i in [0,32)
    int live = 32;
    #pragma unroll
    for (int m = 0; m < 4; m++) {
        int half = live >> 1;
        int mask = 1 << m;
        bool hi = (lane >> m) & 1;
        #pragma unroll
        for (int j = 0; j < half; j++) {
            ull lo_s = add2(v[j],        __shfl_xor_sync(0xffffffffu, v[j],        mask));
            ull hi_s = add2(v[j + half], __shfl_xor_sync(0xffffffffu, v[j + half], mask));
            v[j] = hi ? hi_s : lo_s;
        }
        live = half;
    }
    int s = lane & 15;
    int base = ((s & 1) << 4) | (((s >> 1) & 1) << 3) |
               (((s >> 2) & 1) << 2) | (((s >> 3) & 1) << 1);
    #pragma unroll
    for (int j = 0; j < 2; j++) {
        int i = base + j;                       // original index r*4+p
        float2 f = unpk(v[j]);
        *reinterpret_cast<float2*>(gbuf + (rg8 + (i >> 2)) * BAT + bg8 + 2 * (i & 3)) = f;
    }
}

__global__ void init_kernel(float* __restrict__ out, const float* __restrict__ b_out) {
    int i = blockIdx.x * blockDim.x + threadIdx.x;
    if (i == 0) g_bar = 0u;
    if (i < HID * BAT) {
        g_h1[0][i] = 0.0f; g_h1[1][i] = 0.0f;
        g_h2[0][i] = 0.0f; g_h2[1][i] = 0.0f;
    }
    if (i < BAT * TT) out[i] = b_out[0];
}

__global__ void __launch_bounds__(TPB, 1)
lstm_persistent_kernel(
    const float* __restrict__ x,
    const float* __restrict__ W_ih1, const float* __restrict__ W_hh1,
    const float* __restrict__ b_ih1, const float* __restrict__ b_hh1,
    const float* __restrict__ W_ih2, const float* __restrict__ W_hh2,
    const float* __restrict__ b_ih2, const float* __restrict__ b_hh2,
    const float* __restrict__ W_out, float* __restrict__ out)
{
    extern __shared__ float sm[];
    const int tid  = threadIdx.x;
    const int blk  = blockIdx.x;
    const int lane = tid & 31;
    const int warp = tid >> 5;          // 16 warps

    const int slice = lane & 15;        // k-slice (16-way)
    const int rg8   = (lane >> 4) << 3; // row base: 0 or 8
    const int bg8   = warp << 3;        // batch base (warp-uniform)

    // cell-update mapping: one (unit, batch) per thread
    const int cu = tid >> 7;            // unit 0..3
    const int cb = tid & 127;           // batch 0..127

    // ---- one-time setup: weights -> smem k-major (stride 20), consts, states
    for (int idx = tid; idx < 16 * HID; idx += TPB) {
        int r = idx >> 9, k = idx & 511;               // r = gate*4 + unit
        int row = ((r >> 2) * HID) + blk * 4 + (r & 3);
        sm[OW1 + k * 20 + r] = W_hh1[row * HID + k];
        sm[OW2 + k * 20 + r] = W_ih2[row * HID + k];
        sm[OW3 + k * 20 + r] = W_hh2[row * HID + k];
    }
    if (tid < 16) {
        int row = ((tid >> 2) * HID) + blk * 4 + (tid & 3);
        sm[OCB1 + tid] = b_ih1[row] + b_hh1[row];
        sm[OCW1 + tid] = W_ih1[row];                   // F = 1
        sm[OCB2 + tid] = b_ih2[row] + b_hh2[row];
    }
    if (tid < 4) sm[OCWO + tid] = W_out[blk * 4 + tid];
    for (int idx = tid; idx < 4 * BAT; idx += TPB) {
        sm[OC1 + idx] = 0.0f;
        sm[OC2 + idx] = 0.0f;
    }
    __syncthreads();

    float* wb = sm + OHB + warp * 1024;   // warp-private staging ring
    float* gA = sm + OGA;
    float* gB = sm + OGB;
    unsigned ep = 0;

    // Region r (r = 0..TT): computes cell1(step r) [skip r==TT] and
    // cell2(step r-1) [skip r==0]. Parity p = r&1:
    //   h1: read g_h1[p]   (h1(r-1)), write g_h1[p^1] (h1(r))
    //   h2: read g_h2[p^1] (h2(r-2)), write g_h2[p]   (h2(r-1))
    // All pass inputs were published by region r-1's end barrier.
    for (int r = 0; r <= TT; r++) {
        const int p = r & 1;
        ull acc[8][4];

        // ---- pass A: gates1(r) = W_hh1 . h1(r-1)
        if (r < TT) {
            #pragma unroll
            for (int a = 0; a < 8; a++)
                #pragma unroll
                for (int q = 0; q < 4; q++) acc[a][q] = 0ull;
            pass_accum(g_h1[p], sm + OW1, wb, acc, rg8, bg8, slice, lane);
            reduce_to_gbuf(acc, gA, rg8, bg8, lane);
        }

        // ---- passes B: gates2(r-1) = W_ih2 . h1(r-1) + W_hh2 . h2(r-2)
        if (r > 0) {
            #pragma unroll
            for (int a = 0; a < 8; a++)
                #pragma unroll
                for (int q = 0; q < 4; q++) acc[a][q] = 0ull;
            pass_accum(g_h1[p],     sm + OW2, wb, acc, rg8, bg8, slice, lane);
            pass_accum(g_h2[p ^ 1], sm + OW3, wb, acc, rg8, bg8, slice, lane);
            reduce_to_gbuf(acc, gB, rg8, bg8, lane);
        }
        __syncthreads();   // gate buffers complete for all warps

        // ---- cell2 update (step r-1) + output partial
        if (r > 0) {
            float gi = gB[(cu)      * BAT + cb] + sm[OCB2 + cu];
            float gf = gB[(4 + cu)  * BAT + cb] + sm[OCB2 + 4 + cu];
            float gg = gB[(8 + cu)  * BAT + cb] + sm[OCB2 + 8 + cu];
            float go = gB[(12 + cu) * BAT + cb] + sm[OCB2 + 12 + cu];
            float cc = sm[OC2 + cu * BAT + cb];
            float cn = sigf(gf) * cc + sigf(gi) * tanhf(gg);
            float hn = sigf(go) * tanhf(cn);
            sm[OC2 + cu * BAT + cb] = cn;
            g_h2[p][(blk * 4 + cu) * BAT + cb] = hn;
            gB[cu * BAT + cb] = hn * sm[OCWO + cu];   // own gate-i slot: safe
            __syncthreads();
            if (tid < BAT) {
                float v = gB[tid] + gB[BAT + tid] + gB[2 * BAT + tid] + gB[3 * BAT + tid];
                atomicAdd(&out[tid * TT + (r - 1)], v);
            }
        }

        // ---- cell1 update (step r)
        if (r < TT) {
            float xv;
            if (r < T_IN) {
                xv = x[cb * T_IN + r];
            } else {
                // needs out(r-1) from all blocks' atomics above
                grid_barrier(++ep * NB);
                xv = ldcg32(&out[cb * TT + (r - 1)]);
            }
            float gi = gA[(cu)      * BAT + cb] + xv * sm[OCW1 + cu]      + sm[OCB1 + cu];
            float gf = gA[(4 + cu)  * BAT + cb] + xv * sm[OCW1 + 4 + cu]  + sm[OCB1 + 4 + cu];
            float gg = gA[(8 + cu)  * BAT + cb] + xv * sm[OCW1 + 8 + cu]  + sm[OCB1 + 8 + cu];
            float go = gA[(12 + cu) * BAT + cb] + xv * sm[OCW1 + 12 + cu] + sm[OCB1 + 12 + cu];
            float cc = sm[OC1 + cu * BAT + cb];
            float cn = sigf(gf) * cc + sigf(gi) * tanhf(gg);
            float hn = sigf(go) * tanhf(cn);
            sm[OC1 + cu * BAT + cb] = cn;
            g_h1[p ^ 1][(blk * 4 + cu) * BAT + cb] = hn;

            // end-of-region barrier publishes h1(r) and h2(r-1)
            grid_barrier(++ep * NB);
        }
        // r == TT: only cell2(TT-1) + atomics; kernel end flushes them.
    }
}

extern "C" void kernel_launch(void* const* d_in, const int* in_sizes, int n_in,
                              void* d_out, int out_size) {
    const float* x     = (const float*)d_in[0];
    const float* W_ih1 = (const float*)d_in[1];
    const float* W_hh1 = (const float*)d_in[2];
    const float* b_ih1 = (const float*)d_in[3];
    const float* b_hh1 = (const float*)d_in[4];
    const float* W_ih2 = (const float*)d_in[5];
    const float* W_hh2 = (const float*)d_in[6];
    const float* b_ih2 = (const float*)d_in[7];
    const float* b_hh2 = (const float*)d_in[8];
    const float* W_out = (const float*)d_in[9];
    const float* b_out = (const float*)d_in[10];
    float* out = (float*)d_out;

    cudaFuncSetAttribute(lstm_persistent_kernel,
                         cudaFuncAttributeMaxDynamicSharedMemorySize, SMF * 4);

    init_kernel<<<(BAT * TT + 255) / 256, 256>>>(out, b_out);
    lstm_persistent_kernel<<<NB, TPB, SMF * 4>>>(
        x, W_ih1, W_hh1, b_ih1, b_hh1,
        W_ih2, W_hh2, b_ih2, b_hh2, W_out, out);
}